// round 9
// baseline (speedup 1.0000x reference)
#include <cuda_runtime.h>
#include <float.h>

#define NB 64
#define NK 5
#define ND 1024
#define NH 32
#define NW 32
#define NHW 1024

#define GP 4                            // patches per task
#define NTASK (NB * NHW / GP)           // 16384 tasks
#define TPB 256                         // tasks per batch index (NHW/GP)
#define GRID1 152                       // 1 CTA/SM on GB300 (152 SMs) - all resident
#define NWARP 16                        // warps per CTA

#define RS 5                            // ring slots per warp
#define DPRE 4                          // prefetch depth in chunks
#define SLOT_BYTES 2048                 // GP patches * 32 lanes * 16B
#define CUE_BYTES (2 * NK * ND * 4)     // 40 KB (block range spans <=2 b)
#define SMEM_TOTAL (CUE_BYTES + NWARP * RS * SLOT_BYTES)   // 204800 B

// packed per-(b,k) best: (sortable(sim) << 32) | (1023 - n). Zero at load;
// reset in-kernel after use -> deterministic across graph replays.
__device__ unsigned long long g_best[NB * NK];
__device__ unsigned int g_bar1;          // grid barrier arrive counter
__device__ unsigned int g_bar2;          // epilogue counter (self-reset)

// ---------------------------------------------------------------------------
__device__ __forceinline__ void cpasync16(unsigned int dst, const float4* src) {
    asm volatile("cp.async.cg.shared.global [%0], [%1], 16;"
                 :: "r"(dst), "l"(src) : "memory");
}
__device__ __forceinline__ void cp_commit() {
    asm volatile("cp.async.commit_group;" ::: "memory");
}
__device__ __forceinline__ void cp_waitpre() {
    asm volatile("cp.async.wait_group %0;" :: "n"(DPRE - 1) : "memory");
}
__device__ __forceinline__ void cp_waitall() {
    asm volatile("cp.async.wait_group 0;" ::: "memory");
}
__device__ __forceinline__ void lds_2x64(unsigned long long& a, unsigned long long& b,
                                         unsigned int addr) {
    asm volatile("ld.shared.v2.b64 {%0,%1}, [%2];" : "=l"(a), "=l"(b) : "r"(addr));
}
__device__ __forceinline__ unsigned long long fma2(unsigned long long a,
                                                   unsigned long long b,
                                                   unsigned long long c) {
    unsigned long long d;
    asm("fma.rn.f32x2 %0, %1, %2, %3;" : "=l"(d) : "l"(a), "l"(b), "l"(c));
    return d;
}
__device__ __forceinline__ float unpack_add(unsigned long long v) {
    unsigned int lo, hi;
    asm("mov.b64 {%0,%1}, %2;" : "=r"(lo), "=r"(hi) : "l"(v));
    return __uint_as_float(lo) + __uint_as_float(hi);
}
__device__ __forceinline__ unsigned int ld_acq(const unsigned int* p) {
    unsigned int v;
    asm volatile("ld.acquire.gpu.global.u32 %0, [%1];" : "=r"(v) : "l"(p));
    return v;
}

// ---------------------------------------------------------------------------
// Single persistent kernel:
//   Phase 1: sim[b][k][n] = dot(cue[b][k], patch[b][n]) * rsqrt(||patch||^2)
//            fused running argmax via atomicMax on packed keys.
//            (cue normalization is a positive per-k scale -> argmax-invariant)
//   Grid barrier (all 152 CTAs resident, counter-based, self-resetting).
//   Phase 2: zero-padded 3x3 neighborhood mean around decoded argmax.
// ---------------------------------------------------------------------------
__global__ void __launch_bounds__(512, 1) buddy_kernel(const float* __restrict__ cue,
                                                       const float* __restrict__ patches,
                                                       float* __restrict__ out)
{
    extern __shared__ char smem[];
    const unsigned int sbase = (unsigned int)__cvta_generic_to_shared(smem);

    const int w    = blockIdx.x;
    const int t0   = (int)(((long long)w * NTASK) / GRID1);
    const int t1   = (int)(((long long)(w + 1) * NTASK) / GRID1);
    const int warp = threadIdx.x >> 5;
    const int lane = threadIdx.x & 31;

    const int b0 = t0 / TPB;                       // range spans <=2 b values
    {
        const int nb = (((t1 - 1) / TPB) != b0) ? 2 : 1;
        const float4* cs4 = (const float4*)(cue + (size_t)b0 * NK * ND);
        float4* sd = (float4*)smem;
        for (int i = threadIdx.x; i < nb * (NK * ND / 4); i += 512)
            sd[i] = cs4[i];
    }
    __syncthreads();

    const float4* patches4 = (const float4*)patches;
    const int tw0 = t0 + warp;
    const int nt  = (tw0 < t1) ? ((t1 - tw0 + NWARP - 1) / NWARP) : 0;

    if (nt > 0) {
        const int totq = nt * 8;
        const unsigned int ring = sbase + CUE_BYTES + warp * (RS * SLOT_BYTES);

        // ---- prologue: issue DPRE chunk-groups ----
        int qp = 0;
        int sp = 0;                                // producer slot
#pragma unroll
        for (int i = 0; i < DPRE; i++) {
            if (qp < totq) {
                const int tq = tw0 + (qp >> 3) * NWARP;
                const int u  = qp & 7;
                const size_t gb = (size_t)tq * (GP * ND / 4) + (size_t)u * 32 + lane;
                const unsigned int sdst = ring + sp * SLOT_BYTES + lane * 16;
#pragma unroll
                for (int p = 0; p < GP; p++)
                    cpasync16(sdst + p * 512, patches4 + gb + (size_t)p * (ND / 4));
            }
            cp_commit();
            qp++;
            sp = (sp + 1 == RS) ? 0 : sp + 1;
        }

        unsigned long long bestkey = 0;            // lanes 0..19 meaningful
        int curb = tw0 / TPB;
        int sc = 0;                                // consumer slot

        for (int ti = 0; ti < nt; ti++) {
            const int t  = tw0 + ti * NWARP;
            const int bb = t / TPB;

            if (bb != curb) {                      // batch-boundary flush
                unsigned long long k2 = __shfl_sync(0xffffffffu, bestkey, lane + 10);
                if (bestkey < k2) bestkey = k2;
                k2 = __shfl_sync(0xffffffffu, bestkey, lane + 5);
                if (bestkey < k2) bestkey = k2;
                if (lane < NK) atomicMax(&g_best[curb * NK + lane], bestkey);
                bestkey = 0;
                curb = bb;
            }

            const unsigned int cbase = sbase + (unsigned int)(bb - b0) * (NK * ND * 4);

            unsigned long long acc2[GP][6];
#pragma unroll
            for (int p = 0; p < GP; p++)
#pragma unroll
                for (int j = 0; j < 6; j++) acc2[p][j] = 0ull;

#pragma unroll
            for (int u = 0; u < 8; u++) {
                if (qp < totq) {                   // produce (or dummy commit)
                    const int tq = tw0 + (qp >> 3) * NWARP;
                    const int uq = qp & 7;
                    const size_t gb = (size_t)tq * (GP * ND / 4) + (size_t)uq * 32 + lane;
                    const unsigned int sdst = ring + sp * SLOT_BYTES + lane * 16;
#pragma unroll
                    for (int p = 0; p < GP; p++)
                        cpasync16(sdst + p * 512, patches4 + gb + (size_t)p * (ND / 4));
                }
                cp_commit();
                qp++;
                sp = (sp + 1 == RS) ? 0 : sp + 1;

                cp_waitpre();                      // chunk (qp-1-DPRE) ready

                unsigned long long cl[NK], ch[NK];
                const unsigned int ca = cbase + (unsigned int)(u * 128 + lane * 4) * 4;
#pragma unroll
                for (int k = 0; k < NK; k++)
                    lds_2x64(cl[k], ch[k], ca + (unsigned int)k * (ND * 4));

                const unsigned int sl = ring + sc * SLOT_BYTES + lane * 16;
#pragma unroll
                for (int p = 0; p < GP; p++) {
                    unsigned long long xl, xh;
                    lds_2x64(xl, xh, sl + p * 512);
#pragma unroll
                    for (int k = 0; k < NK; k++)
                        acc2[p][k] = fma2(xl, cl[k], fma2(xh, ch[k], acc2[p][k]));
                    acc2[p][5] = fma2(xl, xl, fma2(xh, xh, acc2[p][5]));
                }
                sc = (sc + 1 == RS) ? 0 : sc + 1;
            }

            // fold f32x2 -> f32, butterfly all-reduce
            float acc[GP][6];
#pragma unroll
            for (int p = 0; p < GP; p++)
#pragma unroll
                for (int j = 0; j < 6; j++) {
                    float s = unpack_add(acc2[p][j]);
#pragma unroll
                    for (int off = 16; off; off >>= 1)
                        s += __shfl_xor_sync(0xffffffffu, s, off);
                    acc[p][j] = s;
                }

            float outv = 0.f, nrm = 1.f;
#pragma unroll
            for (int p = 0; p < GP; p++)
#pragma unroll
                for (int k = 0; k < NK; k++)
                    if (lane == p * NK + k) { outv = acc[p][k]; nrm = acc[p][5]; }

            if (lane < GP * NK) {
                const float sim = outv * rsqrtf(nrm);
                const unsigned int fb = __float_as_uint(sim);
                const unsigned int s  = (fb & 0x80000000u) ? ~fb : (fb | 0x80000000u);
                const int p = lane / NK;
                const int n = (t % TPB) * GP + p;
                const unsigned long long key =
                    ((unsigned long long)s << 32) | (unsigned int)(NHW - 1 - n);
                if (key > bestkey) bestkey = key;
            }
        }

        // final flush
        unsigned long long k2 = __shfl_sync(0xffffffffu, bestkey, lane + 10);
        if (bestkey < k2) bestkey = k2;
        k2 = __shfl_sync(0xffffffffu, bestkey, lane + 5);
        if (bestkey < k2) bestkey = k2;
        if (lane < NK) atomicMax(&g_best[curb * NK + lane], bestkey);

        cp_waitall();                              // drain async queue
    }

    // ---- grid barrier (all 152 CTAs resident) ----
    __syncthreads();
    if (threadIdx.x == 0) {
        __threadfence();
        atomicAdd(&g_bar1, 1u);
        while (ld_acq(&g_bar1) < GRID1) { }
    }
    __syncthreads();

    // ---- Phase 2: 3x3 zero-padded mean. Tasks bk = w, w+152, w+304. ----
    const int tid = threadIdx.x;
    for (int bk = w; bk < NB * NK; bk += GRID1) {
        const int b = bk / NK;
        const unsigned long long key = g_best[bk];
        const int idx = (NHW - 1) - (int)(unsigned int)(key & 0xFFFFFFFFu);
        const int r  = idx >> 5;
        const int c0 = idx & 31;

        const float2* pb = (const float2*)(patches + (size_t)b * NHW * ND);
        float2 acc = make_float2(0.f, 0.f);
#pragma unroll
        for (int dy = -1; dy <= 1; dy++) {
#pragma unroll
            for (int dx = -1; dx <= 1; dx++) {
                const int rr = r + dy;
                const int cc = c0 + dx;
                const bool ok = (rr >= 0) & (rr < NH) & (cc >= 0) & (cc < NW);
                const int rrc = min(max(rr, 0), NH - 1);
                const int ccc = min(max(cc, 0), NW - 1);
                const float wgt = ok ? 1.0f : 0.0f;
                const float2 q = pb[(size_t)(rrc * NW + ccc) * (ND / 2) + tid];
                acc.x = fmaf(wgt, q.x, acc.x);
                acc.y = fmaf(wgt, q.y, acc.y);
            }
        }
        const float inv9 = 1.0f / 9.0f;
        acc.x *= inv9; acc.y *= inv9;
        ((float2*)out)[(size_t)bk * (ND / 2) + tid] = acc;
    }

    // reset this block's g_best entries (only this block read them)
    __syncthreads();
    if (tid == 0) {
        for (int bk = w; bk < NB * NK; bk += GRID1) g_best[bk] = 0ull;
        __threadfence();
        const unsigned int prev = atomicAdd(&g_bar2, 1u);
        if (prev == GRID1 - 1) {                   // last block self-resets barrier
            g_bar1 = 0u;
            g_bar2 = 0u;
            __threadfence();
        }
    }
}

// ---------------------------------------------------------------------------
extern "C" void kernel_launch(void* const* d_in, const int* in_sizes, int n_in,
                              void* d_out, int out_size)
{
    const float* cue     = (const float*)d_in[0];   // (64,5,1024)
    const float* patches = (const float*)d_in[1];   // (64,32,32,1024)
    float*       out     = (float*)d_out;           // (64,5,1024)

    (void)in_sizes; (void)n_in; (void)out_size;

    cudaFuncSetAttribute(buddy_kernel,
                         cudaFuncAttributeMaxDynamicSharedMemorySize, SMEM_TOTAL);

    buddy_kernel<<<GRID1, 512, SMEM_TOTAL>>>(cue, patches, out);
}

// round 10
// speedup vs baseline: 1.0118x; 1.0118x over previous
#include <cuda_runtime.h>
#include <float.h>

#define NB 64
#define NK 5
#define ND 1024
#define NH 32
#define NW 32
#define NHW 1024

#define GP 4                            // patches per task
#define NTASK (NB * NHW / GP)           // 16384 tasks
#define TPB 256                         // tasks per batch index (NHW/GP)
#define GRID1 152                       // 1 CTA/SM on GB300 (152 SMs)
#define NWARP 16                        // warps per CTA

#define RS 5                            // ring slots per warp
#define DPRE 4                          // prefetch depth in chunks
#define SLOT_BYTES 2048                 // GP patches * 32 lanes * 16B
#define CUE_BYTES (2 * NK * ND * 4)     // 40 KB (block range spans <=2 b)
#define SMEM_TOTAL (CUE_BYTES + NWARP * RS * SLOT_BYTES)   // 204800 B

// packed per-(b,k) best: (sortable(sim) << 32) | (1023 - n). Zero at load;
// gather_kernel re-zeroes after consuming -> deterministic across replays.
__device__ unsigned long long g_best[NB * NK];

// ---------------------------------------------------------------------------
__device__ __forceinline__ void cpasync16(unsigned int dst, const float4* src) {
    asm volatile("cp.async.cg.shared.global [%0], [%1], 16;"
                 :: "r"(dst), "l"(src) : "memory");
}
__device__ __forceinline__ void cp_commit() {
    asm volatile("cp.async.commit_group;" ::: "memory");
}
__device__ __forceinline__ void cp_waitpre() {
    asm volatile("cp.async.wait_group %0;" :: "n"(DPRE - 1) : "memory");
}
__device__ __forceinline__ void lds_2x64(unsigned long long& a, unsigned long long& b,
                                         unsigned int addr) {
    asm volatile("ld.shared.v2.b64 {%0,%1}, [%2];" : "=l"(a), "=l"(b) : "r"(addr));
}
__device__ __forceinline__ unsigned long long fma2(unsigned long long a,
                                                   unsigned long long b,
                                                   unsigned long long c) {
    unsigned long long d;
    asm("fma.rn.f32x2 %0, %1, %2, %3;" : "=l"(d) : "l"(a), "l"(b), "l"(c));
    return d;
}
__device__ __forceinline__ float unpack_add(unsigned long long v) {
    unsigned int lo, hi;
    asm("mov.b64 {%0,%1}, %2;" : "=r"(lo), "=r"(hi) : "l"(v));
    return __uint_as_float(lo) + __uint_as_float(hi);
}

// ---------------------------------------------------------------------------
// Kernel 1 (persistent, cp.async-pipelined, fused sims+argmax):
//   sim[b][k][n] = dot(cue[b][k], patch[b][n]) * rsqrt(||patch||^2)
// (cue normalization is a positive per-k scale -> argmax-invariant, skipped)
// 16 warps/SM; per-warp ring of RS chunk slots, DPRE chunks in flight via
// cp.async; dummy commit_groups at the tail keep wait_group exact.
// Signals PDL dependents after the final argmax flush.
// ---------------------------------------------------------------------------
__global__ void __launch_bounds__(512, 1) sims_kernel(const float* __restrict__ cue,
                                                      const float* __restrict__ patches)
{
    extern __shared__ char smem[];
    const unsigned int sbase = (unsigned int)__cvta_generic_to_shared(smem);

    const int w    = blockIdx.x;
    const int t0   = (int)(((long long)w * NTASK) / GRID1);
    const int t1   = (int)(((long long)(w + 1) * NTASK) / GRID1);
    const int warp = threadIdx.x >> 5;
    const int lane = threadIdx.x & 31;

    const int b0 = t0 / TPB;                       // range spans <=2 b values
    {
        const int nb = (((t1 - 1) / TPB) != b0) ? 2 : 1;
        const float4* cs4 = (const float4*)(cue + (size_t)b0 * NK * ND);
        float4* sd = (float4*)smem;
        for (int i = threadIdx.x; i < nb * (NK * ND / 4); i += 512)
            sd[i] = cs4[i];
    }
    __syncthreads();

    const float4* patches4 = (const float4*)patches;
    const int tw0 = t0 + warp;
    const int nt  = (tw0 < t1) ? ((t1 - tw0 + NWARP - 1) / NWARP) : 0;

    if (nt > 0) {
        const int totq = nt * 8;
        const unsigned int ring = sbase + CUE_BYTES + warp * (RS * SLOT_BYTES);

        // ---- prologue: issue DPRE chunk-groups ----
        int qp = 0;
        int sp = 0;                                // producer slot
#pragma unroll
        for (int i = 0; i < DPRE; i++) {
            if (qp < totq) {
                const int tq = tw0 + (qp >> 3) * NWARP;
                const int u  = qp & 7;
                const size_t gb = (size_t)tq * (GP * ND / 4) + (size_t)u * 32 + lane;
                const unsigned int sdst = ring + sp * SLOT_BYTES + lane * 16;
#pragma unroll
                for (int p = 0; p < GP; p++)
                    cpasync16(sdst + p * 512, patches4 + gb + (size_t)p * (ND / 4));
            }
            cp_commit();
            qp++;
            sp = (sp + 1 == RS) ? 0 : sp + 1;
        }

        unsigned long long bestkey = 0;            // lanes 0..19 meaningful
        int curb = tw0 / TPB;
        int sc = 0;                                // consumer slot

        for (int ti = 0; ti < nt; ti++) {
            const int t  = tw0 + ti * NWARP;
            const int bb = t / TPB;

            if (bb != curb) {                      // batch-boundary flush
                unsigned long long k2 = __shfl_sync(0xffffffffu, bestkey, lane + 10);
                if (bestkey < k2) bestkey = k2;
                k2 = __shfl_sync(0xffffffffu, bestkey, lane + 5);
                if (bestkey < k2) bestkey = k2;
                if (lane < NK) atomicMax(&g_best[curb * NK + lane], bestkey);
                bestkey = 0;
                curb = bb;
            }

            const unsigned int cbase = sbase + (unsigned int)(bb - b0) * (NK * ND * 4);

            unsigned long long acc2[GP][6];
#pragma unroll
            for (int p = 0; p < GP; p++)
#pragma unroll
                for (int j = 0; j < 6; j++) acc2[p][j] = 0ull;

#pragma unroll
            for (int u = 0; u < 8; u++) {
                if (qp < totq) {                   // produce (or dummy commit)
                    const int tq = tw0 + (qp >> 3) * NWARP;
                    const int uq = qp & 7;
                    const size_t gb = (size_t)tq * (GP * ND / 4) + (size_t)uq * 32 + lane;
                    const unsigned int sdst = ring + sp * SLOT_BYTES + lane * 16;
#pragma unroll
                    for (int p = 0; p < GP; p++)
                        cpasync16(sdst + p * 512, patches4 + gb + (size_t)p * (ND / 4));
                }
                cp_commit();
                qp++;
                sp = (sp + 1 == RS) ? 0 : sp + 1;

                cp_waitpre();                      // chunk (qp-1-DPRE) ready

                unsigned long long cl[NK], ch[NK];
                const unsigned int ca = cbase + (unsigned int)(u * 128 + lane * 4) * 4;
#pragma unroll
                for (int k = 0; k < NK; k++)
                    lds_2x64(cl[k], ch[k], ca + (unsigned int)k * (ND * 4));

                const unsigned int sl = ring + sc * SLOT_BYTES + lane * 16;
#pragma unroll
                for (int p = 0; p < GP; p++) {
                    unsigned long long xl, xh;
                    lds_2x64(xl, xh, sl + p * 512);
#pragma unroll
                    for (int k = 0; k < NK; k++)
                        acc2[p][k] = fma2(xl, cl[k], fma2(xh, ch[k], acc2[p][k]));
                    acc2[p][5] = fma2(xl, xl, fma2(xh, xh, acc2[p][5]));
                }
                sc = (sc + 1 == RS) ? 0 : sc + 1;
            }

            // fold f32x2 -> f32, butterfly all-reduce
            float acc[GP][6];
#pragma unroll
            for (int p = 0; p < GP; p++)
#pragma unroll
                for (int j = 0; j < 6; j++) {
                    float s = unpack_add(acc2[p][j]);
#pragma unroll
                    for (int off = 16; off; off >>= 1)
                        s += __shfl_xor_sync(0xffffffffu, s, off);
                    acc[p][j] = s;
                }

            float outv = 0.f, nrm = 1.f;
#pragma unroll
            for (int p = 0; p < GP; p++)
#pragma unroll
                for (int k = 0; k < NK; k++)
                    if (lane == p * NK + k) { outv = acc[p][k]; nrm = acc[p][5]; }

            if (lane < GP * NK) {
                const float sim = outv * rsqrtf(nrm);
                const unsigned int fb = __float_as_uint(sim);
                const unsigned int s  = (fb & 0x80000000u) ? ~fb : (fb | 0x80000000u);
                const int p = lane / NK;
                const int n = (t % TPB) * GP + p;
                const unsigned long long key =
                    ((unsigned long long)s << 32) | (unsigned int)(NHW - 1 - n);
                if (key > bestkey) bestkey = key;
            }
        }

        // final flush
        unsigned long long k2 = __shfl_sync(0xffffffffu, bestkey, lane + 10);
        if (bestkey < k2) bestkey = k2;
        k2 = __shfl_sync(0xffffffffu, bestkey, lane + 5);
        if (bestkey < k2) bestkey = k2;
        if (lane < NK) atomicMax(&g_best[curb * NK + lane], bestkey);
    }

    // PDL trigger: this CTA's argmax contributions are flushed; dependents may
    // launch once ALL CTAs have signaled (trigger point flushes memory).
    __syncthreads();
    if (threadIdx.x == 0) {
        __threadfence();
        asm volatile("griddepcontrol.launch_dependents;" ::: "memory");
    }
}

// ---------------------------------------------------------------------------
// Kernel 2 (PDL dependent): zero-padded 3x3 neighborhood mean around decoded
// argmax. Launched with programmatic serialization: blocks spin up during the
// sims tail and park on griddepcontrol.wait. 9 clamped unconditional loads
// front-batch -> MLP 9. Resets g_best for next graph replay.
// ---------------------------------------------------------------------------
__global__ void __launch_bounds__(256) gather_kernel(const float* __restrict__ patches,
                                                     float* __restrict__ out)
{
    asm volatile("griddepcontrol.wait;" ::: "memory");

    const int bk  = blockIdx.x;
    const int b   = bk / NK;
    const int tid = threadIdx.x;

    // uniform per-block load (L1 broadcast); every thread reads before the
    // barrier, tid0 resets after it.
    const unsigned long long key = g_best[bk];
    const int idx = (NHW - 1) - (int)(unsigned int)(key & 0xFFFFFFFFu);
    __syncthreads();
    if (tid == 0) g_best[bk] = 0ull;

    const int r  = idx >> 5;
    const int c0 = idx & 31;

    const float4* pb = (const float4*)(patches + (size_t)b * NHW * ND);
    float4 acc = make_float4(0.f, 0.f, 0.f, 0.f);
#pragma unroll
    for (int dy = -1; dy <= 1; dy++) {
#pragma unroll
        for (int dx = -1; dx <= 1; dx++) {
            const int rr = r + dy;
            const int cc = c0 + dx;
            const bool ok = (rr >= 0) & (rr < NH) & (cc >= 0) & (cc < NW);
            const int rrc = min(max(rr, 0), NH - 1);
            const int ccc = min(max(cc, 0), NW - 1);
            const float wgt = ok ? 1.0f : 0.0f;
            const float4 q = pb[(size_t)(rrc * NW + ccc) * (ND / 4) + tid];
            acc.x = fmaf(wgt, q.x, acc.x);
            acc.y = fmaf(wgt, q.y, acc.y);
            acc.z = fmaf(wgt, q.z, acc.z);
            acc.w = fmaf(wgt, q.w, acc.w);
        }
    }
    const float inv9 = 1.0f / 9.0f;
    acc.x *= inv9; acc.y *= inv9; acc.z *= inv9; acc.w *= inv9;
    ((float4*)out)[(size_t)bk * (ND / 4) + tid] = acc;
}

// ---------------------------------------------------------------------------
extern "C" void kernel_launch(void* const* d_in, const int* in_sizes, int n_in,
                              void* d_out, int out_size)
{
    const float* cue     = (const float*)d_in[0];   // (64,5,1024)
    const float* patches = (const float*)d_in[1];   // (64,32,32,1024)
    float*       out     = (float*)d_out;           // (64,5,1024)

    (void)in_sizes; (void)n_in; (void)out_size;

    cudaFuncSetAttribute(sims_kernel,
                         cudaFuncAttributeMaxDynamicSharedMemorySize, SMEM_TOTAL);

    sims_kernel<<<GRID1, 512, SMEM_TOTAL>>>(cue, patches);

    // gather as a programmatic dependent launch: overlaps its launch latency
    // with the sims tail, waits in-kernel for the trigger.
    cudaLaunchConfig_t cfg = {};
    cfg.gridDim  = dim3(NB * NK, 1, 1);
    cfg.blockDim = dim3(256, 1, 1);
    cfg.dynamicSmemBytes = 0;
    cudaLaunchAttribute attrs[1];
    attrs[0].id = cudaLaunchAttributeProgrammaticStreamSerialization;
    attrs[0].val.programmaticStreamSerializationAllowed = 1;
    cfg.attrs = attrs;
    cfg.numAttrs = 1;
    cudaLaunchKernelEx(&cfg, gather_kernel, patches, out);
}